// round 1
// baseline (speedup 1.0000x reference)
#include <cuda_runtime.h>
#include <math.h>

#define KDIM 384
#define NEL 25165824   // 16*64*64*384

static __device__ float g_xd[NEL];   // conv output, channels-last
static __device__ float g_xs[NEL];   // xs (pre-DCT)
static __device__ float g_z [NEL];   // silu(z)
static __device__ float g_s [NEL];   // combined modulation scalar
static __device__ float g_f1[NEL];
static __device__ float g_f2[NEL];
static __device__ float g_W[4096];   // 64x64 DCT-II matrix

// ---------------------------------------------------------------- build W
__global__ void build_w_k() {
    int i = blockIdx.x * 256 + threadIdx.x;
    int n = i >> 6, h = i & 63;
    float v = cosf((float)n * (((float)h + 0.5f) * (3.14159265358979323846f / 64.0f)))
            * 0.17677669529663687f;                 // sqrt(2/64)
    if (n == 0) v *= 0.70710678118654752f;
    g_W[i] = v;
}

// ---------------------------------------------------------------- depthwise conv 3x3, NCHW -> NHWC
__global__ void dwconv_k(const float* __restrict__ x, const float* __restrict__ w9,
                         const float* __restrict__ bias, float* __restrict__ outp)
{
    const int bh = blockIdx.x;          // b*64 + h
    const int c  = threadIdx.x;         // 0..383
    const int b  = bh >> 6, h = bh & 63;
    const float* xp = x + (size_t)(b * 384 + c) * 64 * 64;
    float k0 = w9[c*9+0], k1 = w9[c*9+1], k2 = w9[c*9+2];
    float k3 = w9[c*9+3], k4 = w9[c*9+4], k5 = w9[c*9+5];
    float k6 = w9[c*9+6], k7 = w9[c*9+7], k8 = w9[c*9+8];
    const float bi = bias[c];
    const float* r0 = (h > 0)  ? xp + (h-1)*64 : 0;
    const float* r1 = xp + h*64;
    const float* r2 = (h < 63) ? xp + (h+1)*64 : 0;
    float a0 = 0.f, a1 = 0.f, a2 = 0.f;
    float m0 = r0 ? r0[0] : 0.f;
    float m1 = r1[0];
    float m2 = r2 ? r2[0] : 0.f;
    float* ob = outp + (size_t)bh * 64 * 384 + c;
    #pragma unroll 4
    for (int w = 0; w < 64; w++) {
        float n0, n1, n2;
        if (w < 63) {
            n0 = r0 ? r0[w+1] : 0.f;
            n1 = r1[w+1];
            n2 = r2 ? r2[w+1] : 0.f;
        } else { n0 = n1 = n2 = 0.f; }
        float acc = bi
            + a0*k0 + m0*k1 + n0*k2
            + a1*k3 + m1*k4 + n1*k5
            + a2*k6 + m2*k7 + n2*k8;
        ob[(size_t)w * 384] = acc;
        a0 = m0; a1 = m1; a2 = m2;
        m0 = n0; m1 = n1; m2 = n2;
    }
}

// ---------------------------------------------------------------- SGEMM: out[m,n] = sum_k A[m,k]*Wt[n,k] (+epilogue)
// MODE 0: lin  -> cols<384 to o0 (xs), cols>=384 silu -> o1 (z)
// MODE 1: tok  -> gelu + modulation scalar s -> o0
// MODE 2: out  -> plain bias -> o0
template<int MODE>
__global__ void __launch_bounds__(256, 2) sgemm_k(
    const float* __restrict__ A, const float* __restrict__ Wt,
    const float* __restrict__ bias,
    float* __restrict__ o0, float* __restrict__ o1,
    const float* __restrict__ cp, const float* __restrict__ ap)
{
    __shared__ float As[2][8][132];
    __shared__ float Bs[2][8][132];
    const int t  = threadIdx.x;
    const int bx = blockIdx.x, by = blockIdx.y;
    const int lr = t >> 1;
    const int lk = (t & 1) << 2;
    const float* Ap = A  + (size_t)(by * 128 + lr) * KDIM + lk;
    const float* Bp = Wt + (size_t)(bx * 128 + lr) * KDIM + lk;
    float4 av = *(const float4*)Ap;
    float4 bv = *(const float4*)Bp;
    As[0][lk+0][lr] = av.x; As[0][lk+1][lr] = av.y; As[0][lk+2][lr] = av.z; As[0][lk+3][lr] = av.w;
    Bs[0][lk+0][lr] = bv.x; Bs[0][lk+1][lr] = bv.y; Bs[0][lk+2][lr] = bv.z; Bs[0][lk+3][lr] = bv.w;
    __syncthreads();
    const int tx = t & 15, ty = t >> 4;
    float acc[8][8];
    #pragma unroll
    for (int i = 0; i < 8; i++)
        #pragma unroll
        for (int j = 0; j < 8; j++) acc[i][j] = 0.f;
    const int NT = KDIM / 8;
    #pragma unroll 1
    for (int kt = 0; kt < NT; kt++) {
        const int buf = kt & 1;
        if (kt + 1 < NT) {
            av = *(const float4*)(Ap + (kt+1)*8);
            bv = *(const float4*)(Bp + (kt+1)*8);
        }
        #pragma unroll
        for (int kk = 0; kk < 8; kk++) {
            float4 a0 = *(const float4*)&As[buf][kk][ty*8];
            float4 a1 = *(const float4*)&As[buf][kk][ty*8+4];
            float4 b0 = *(const float4*)&Bs[buf][kk][tx*8];
            float4 b1 = *(const float4*)&Bs[buf][kk][tx*8+4];
            float ar[8] = {a0.x,a0.y,a0.z,a0.w,a1.x,a1.y,a1.z,a1.w};
            float br[8] = {b0.x,b0.y,b0.z,b0.w,b1.x,b1.y,b1.z,b1.w};
            #pragma unroll
            for (int i = 0; i < 8; i++)
                #pragma unroll
                for (int j = 0; j < 8; j++)
                    acc[i][j] = fmaf(ar[i], br[j], acc[i][j]);
        }
        if (kt + 1 < NT) {
            const int nb = buf ^ 1;
            As[nb][lk+0][lr] = av.x; As[nb][lk+1][lr] = av.y; As[nb][lk+2][lr] = av.z; As[nb][lk+3][lr] = av.w;
            Bs[nb][lk+0][lr] = bv.x; Bs[nb][lk+1][lr] = bv.y; Bs[nb][lk+2][lr] = bv.z; Bs[nb][lk+3][lr] = bv.w;
            __syncthreads();
        }
    }
    const int m0 = by * 128 + ty * 8;
    const int n0 = bx * 128 + tx * 8;
    float bb[8];
    #pragma unroll
    for (int j = 0; j < 8; j++) bb[j] = bias[n0 + j];

    if (MODE == 0) {
        if (n0 < 384) {
            #pragma unroll
            for (int i = 0; i < 8; i++) {
                float r[8];
                #pragma unroll
                for (int j = 0; j < 8; j++) r[j] = acc[i][j] + bb[j];
                float4* dst = (float4*)(o0 + (size_t)(m0+i)*384 + n0);
                dst[0] = make_float4(r[0],r[1],r[2],r[3]);
                dst[1] = make_float4(r[4],r[5],r[6],r[7]);
            }
        } else {
            #pragma unroll
            for (int i = 0; i < 8; i++) {
                float r[8];
                #pragma unroll
                for (int j = 0; j < 8; j++) {
                    float v = acc[i][j] + bb[j];
                    r[j] = v / (1.0f + expf(-v));            // silu
                }
                float4* dst = (float4*)(o1 + (size_t)(m0+i)*384 + (n0 - 384));
                dst[0] = make_float4(r[0],r[1],r[2],r[3]);
                dst[1] = make_float4(r[4],r[5],r[6],r[7]);
            }
        }
    } else if (MODE == 1) {
        const float c0 = cp[0], al = ap[0];
        const float ss = (1.0f + 0.5f * al) / (c0 + 1e-8f);
        const float kp = 3.14159265358979323846f / 64.0f;
        const float kp2 = kp * kp;
        #pragma unroll
        for (int i = 0; i < 8; i++) {
            int m = m0 + i;
            int h = (m >> 6) & 63, w = m & 63;
            float e = kp2 * (float)(h*h + w*w);
            float r[8];
            #pragma unroll
            for (int j = 0; j < 8; j++) {
                float v  = acc[i][j] + bb[j];
                float tg = 0.5f * v * (1.0f + erff(v * 0.70710678118654752f)); // exact gelu
                float ct = c0 * tg;
                r[j] = (cosf(ct) + sinf(ct) * ss) * expf(-e * tg);
            }
            float4* dst = (float4*)(o0 + (size_t)m * 384 + n0);
            dst[0] = make_float4(r[0],r[1],r[2],r[3]);
            dst[1] = make_float4(r[4],r[5],r[6],r[7]);
        }
    } else {
        #pragma unroll
        for (int i = 0; i < 8; i++) {
            float r[8];
            #pragma unroll
            for (int j = 0; j < 8; j++) r[j] = acc[i][j] + bb[j];
            float4* dst = (float4*)(o0 + (size_t)(m0+i)*384 + n0);
            dst[0] = make_float4(r[0],r[1],r[2],r[3]);
            dst[1] = make_float4(r[4],r[5],r[6],r[7]);
        }
    }
}

// ---------------------------------------------------------------- batched 64-pt cosine transform
// out[bb,i,j] = sum_k Weff[i,k] * X[bb,k,j]     rows stride ldRow, 64 rows per batch
// FWD: Weff = W (DCT), else Weff = W^T (IDCT). MOD: multiply by S elementwise.
template<bool FWD, bool MOD>
__global__ void __launch_bounds__(256) dct_k(
    float* __restrict__ out, const float* __restrict__ X,
    const float* __restrict__ S, int ldRow)
{
    __shared__ float Ws[64][64];
    __shared__ float Xs[64][128];
    const int t  = threadIdx.x;
    const int bb = blockIdx.y;
    const int j0 = blockIdx.x << 7;
    for (int idx = t; idx < 4096; idx += 256) {
        int k = idx >> 6, i = idx & 63;
        Ws[k][i] = FWD ? g_W[(i << 6) + k] : g_W[(k << 6) + i];
    }
    const float* Xb = X + (size_t)bb * 64 * ldRow + j0;
    for (int f = t; f < 2048; f += 256) {
        int row = f >> 5, col = (f & 31) << 2;
        *(float4*)&Xs[row][col] = *(const float4*)(Xb + (size_t)row * ldRow + col);
    }
    __syncthreads();
    const int tx = t & 15, ty = t >> 4;
    const int i0 = ty << 2, jj = tx << 3;
    float acc[4][8];
    #pragma unroll
    for (int a = 0; a < 4; a++)
        #pragma unroll
        for (int b2 = 0; b2 < 8; b2++) acc[a][b2] = 0.f;
    #pragma unroll 8
    for (int k = 0; k < 64; k++) {
        float4 a  = *(const float4*)&Ws[k][i0];
        float4 b0 = *(const float4*)&Xs[k][jj];
        float4 b1 = *(const float4*)&Xs[k][jj + 4];
        float ar[4] = {a.x, a.y, a.z, a.w};
        float br[8] = {b0.x,b0.y,b0.z,b0.w,b1.x,b1.y,b1.z,b1.w};
        #pragma unroll
        for (int ii = 0; ii < 4; ii++)
            #pragma unroll
            for (int j = 0; j < 8; j++)
                acc[ii][j] = fmaf(ar[ii], br[j], acc[ii][j]);
    }
    float* ob = out + (size_t)bb * 64 * ldRow + j0;
    const float* sb = S + (size_t)bb * 64 * ldRow + j0;
    #pragma unroll
    for (int ii = 0; ii < 4; ii++) {
        size_t off = (size_t)(i0 + ii) * ldRow + jj;
        float4 r0 = make_float4(acc[ii][0],acc[ii][1],acc[ii][2],acc[ii][3]);
        float4 r1 = make_float4(acc[ii][4],acc[ii][5],acc[ii][6],acc[ii][7]);
        if (MOD) {
            float4 s0 = *(const float4*)(sb + off);
            float4 s1 = *(const float4*)(sb + off + 4);
            r0.x *= s0.x; r0.y *= s0.y; r0.z *= s0.z; r0.w *= s0.w;
            r1.x *= s1.x; r1.y *= s1.y; r1.z *= s1.z; r1.w *= s1.w;
        }
        *(float4*)(ob + off)     = r0;
        *(float4*)(ob + off + 4) = r1;
    }
}

// ---------------------------------------------------------------- LayerNorm(C=384) * pre-computed silu(z)
__global__ void ln_silu_k(const float* __restrict__ xin, const float* __restrict__ zs,
                          const float* __restrict__ gam, const float* __restrict__ bet,
                          float* __restrict__ out)
{
    const int row = blockIdx.x;
    const int t = threadIdx.x;            // 128
    const float* xr = xin + (size_t)row * 384;
    float v0 = xr[t], v1 = xr[t + 128], v2 = xr[t + 256];
    float s = v0 + v1 + v2;
    __shared__ float r1[4], r2[4];
    #pragma unroll
    for (int o = 16; o; o >>= 1) s += __shfl_xor_sync(0xffffffffu, s, o);
    if ((t & 31) == 0) r1[t >> 5] = s;
    __syncthreads();
    float mu = (r1[0] + r1[1] + r1[2] + r1[3]) * (1.0f / 384.0f);
    float d0 = v0 - mu, d1 = v1 - mu, d2 = v2 - mu;
    float q = d0*d0 + d1*d1 + d2*d2;
    #pragma unroll
    for (int o = 16; o; o >>= 1) q += __shfl_xor_sync(0xffffffffu, q, o);
    if ((t & 31) == 0) r2[t >> 5] = q;
    __syncthreads();
    float var = (r2[0] + r2[1] + r2[2] + r2[3]) * (1.0f / 384.0f);
    float inv = rsqrtf(var + 1e-5f);
    const float* zr = zs + (size_t)row * 384;
    float* orow = out + (size_t)row * 384;
    orow[t]       = (d0 * inv * gam[t]       + bet[t])       * zr[t];
    orow[t + 128] = (d1 * inv * gam[t + 128] + bet[t + 128]) * zr[t + 128];
    orow[t + 256] = (d2 * inv * gam[t + 256] + bet[t + 256]) * zr[t + 256];
}

// ---------------------------------------------------------------- launcher
extern "C" void kernel_launch(void* const* d_in, const int* in_sizes, int n_in,
                              void* d_out, int out_size)
{
    const float* x     = (const float*)d_in[0];
    const float* freq  = (const float*)d_in[1];
    const float* dw_w  = (const float*)d_in[2];
    const float* dw_b  = (const float*)d_in[3];
    const float* lin_w = (const float*)d_in[4];
    const float* lin_b = (const float*)d_in[5];
    const float* tok_w = (const float*)d_in[6];
    const float* tok_b = (const float*)d_in[7];
    const float* ln_g  = (const float*)d_in[8];
    const float* ln_b  = (const float*)d_in[9];
    const float* out_w = (const float*)d_in[10];
    const float* out_b = (const float*)d_in[11];
    const float* cp    = (const float*)d_in[12];
    const float* ap    = (const float*)d_in[13];
    float* out = (float*)d_out;

    float *pxd, *pxs, *pz, *ps, *pf1, *pf2;
    cudaGetSymbolAddress((void**)&pxd, g_xd);
    cudaGetSymbolAddress((void**)&pxs, g_xs);
    cudaGetSymbolAddress((void**)&pz,  g_z);
    cudaGetSymbolAddress((void**)&ps,  g_s);
    cudaGetSymbolAddress((void**)&pf1, g_f1);
    cudaGetSymbolAddress((void**)&pf2, g_f2);

    build_w_k<<<16, 256>>>();
    dwconv_k<<<1024, 384>>>(x, dw_w, dw_b, pxd);
    // xz = xd @ lin_w^T : xs + silu(z)
    sgemm_k<0><<<dim3(6, 512), 256>>>(pxd, lin_w, lin_b, pxs, pz, nullptr, nullptr);
    // t = gelu(freq @ tok_w^T) -> modulation scalar s
    sgemm_k<1><<<dim3(3, 512), 256>>>(freq, tok_w, tok_b, ps, nullptr, cp, ap);
    // DCT over h (contract rows of stride 24576)
    dct_k<true,  false><<<dim3(192, 16),  256>>>(pf1, pxs, pf1, 24576);
    // DCT over w + modulate by s (contract rows of stride 384)
    dct_k<true,  true ><<<dim3(3,  1024), 256>>>(pf2, pf1, ps, 384);
    // IDCT over n
    dct_k<false, false><<<dim3(192, 16),  256>>>(pf1, pf2, pf1, 24576);
    // IDCT over m
    dct_k<false, false><<<dim3(3,  1024), 256>>>(pf2, pf1, ps, 384);
    // layernorm * silu(z)
    ln_silu_k<<<65536, 128>>>(pf2, pz, ln_g, ln_b, pf1);
    // out = xo @ out_w^T + out_b
    sgemm_k<2><<<dim3(3, 512), 256>>>(pf1, out_w, out_b, out, nullptr, nullptr, nullptr);
}

// round 3
// speedup vs baseline: 1.4241x; 1.4241x over previous
#include <cuda_runtime.h>
#include <cuda_bf16.h>
#include <math.h>
#include <stdint.h>

#define KDIM 384
#define NEL 25165824   // 16*64*64*384

static __device__ float g_xd[NEL];   // conv output, channels-last
static __device__ float g_xs[NEL];   // xs (pre-DCT)
static __device__ float g_z [NEL];   // silu(z)
static __device__ float g_s [NEL];   // combined modulation scalar
static __device__ float g_f1[NEL];
static __device__ float g_f2[NEL];
static __device__ float g_W[4096];   // 64x64 DCT-II matrix

// ================================================================ helpers
__device__ __forceinline__ uint32_t smem_u32(const void* p) {
    uint32_t a;
    asm("{ .reg .u64 t; cvta.to.shared.u64 t, %1; cvt.u32.u64 %0, t; }" : "=r"(a) : "l"(p));
    return a;
}

__device__ __forceinline__ void ldsm4(uint32_t (&r)[4], uint32_t addr) {
    asm volatile("ldmatrix.sync.aligned.m8n8.x4.shared.b16 {%0,%1,%2,%3}, [%4];"
                 : "=r"(r[0]), "=r"(r[1]), "=r"(r[2]), "=r"(r[3]) : "r"(addr));
}

__device__ __forceinline__ void mma16816(float (&d)[4], const uint32_t (&a)[4],
                                         uint32_t b0, uint32_t b1) {
    asm volatile(
        "mma.sync.aligned.m16n8k16.row.col.f32.bf16.bf16.f32 "
        "{%0,%1,%2,%3}, {%4,%5,%6,%7}, {%8,%9}, {%0,%1,%2,%3};"
        : "+f"(d[0]), "+f"(d[1]), "+f"(d[2]), "+f"(d[3])
        : "r"(a[0]), "r"(a[1]), "r"(a[2]), "r"(a[3]), "r"(b0), "r"(b1));
}

__device__ __forceinline__ unsigned swz(unsigned off) {
    return off ^ ((off >> 3) & 0x70);
}

// convert float4 -> hi/lo bf16 pairs and store into swizzled 128B row
// row layout: [hi: 32 bf16 (64B)][lo: 32 bf16 (64B)]
__device__ __forceinline__ void st_split(char* base, int row, int colf, float4 v) {
    __nv_bfloat16 h0 = __float2bfloat16(v.x), h1 = __float2bfloat16(v.y),
                  h2 = __float2bfloat16(v.z), h3 = __float2bfloat16(v.w);
    float l0 = v.x - __bfloat162float(h0), l1 = v.y - __bfloat162float(h1),
          l2 = v.z - __bfloat162float(h2), l3 = v.w - __bfloat162float(h3);
    __nv_bfloat16 g0 = __float2bfloat16(l0), g1 = __float2bfloat16(l1),
                  g2 = __float2bfloat16(l2), g3 = __float2bfloat16(l3);
    unsigned hi0 = ((unsigned)__bfloat16_as_ushort(h1) << 16) | __bfloat16_as_ushort(h0);
    unsigned hi1 = ((unsigned)__bfloat16_as_ushort(h3) << 16) | __bfloat16_as_ushort(h2);
    unsigned lo0 = ((unsigned)__bfloat16_as_ushort(g1) << 16) | __bfloat16_as_ushort(g0);
    unsigned lo1 = ((unsigned)__bfloat16_as_ushort(g3) << 16) | __bfloat16_as_ushort(g2);
    unsigned off = (unsigned)row * 128 + (unsigned)colf * 2;
    *(uint2*)(base + swz(off))      = make_uint2(hi0, hi1);
    *(uint2*)(base + swz(off + 64)) = make_uint2(lo0, lo1);
}

// ================================================================ build W
__global__ void build_w_k() {
    int i = blockIdx.x * 256 + threadIdx.x;
    int n = i >> 6, h = i & 63;
    float v = cosf((float)n * (((float)h + 0.5f) * (3.14159265358979323846f / 64.0f)))
            * 0.17677669529663687f;
    if (n == 0) v *= 0.70710678118654752f;
    g_W[i] = v;
}

// ================================================================ depthwise conv 3x3, NCHW -> NHWC
__global__ void dwconv_k(const float* __restrict__ x, const float* __restrict__ w9,
                         const float* __restrict__ bias, float* __restrict__ outp)
{
    const int bh = blockIdx.x;
    const int c  = threadIdx.x;
    const int b  = bh >> 6, h = bh & 63;
    const float* xp = x + (size_t)(b * 384 + c) * 64 * 64;
    float k0 = w9[c*9+0], k1 = w9[c*9+1], k2 = w9[c*9+2];
    float k3 = w9[c*9+3], k4 = w9[c*9+4], k5 = w9[c*9+5];
    float k6 = w9[c*9+6], k7 = w9[c*9+7], k8 = w9[c*9+8];
    const float bi = bias[c];
    const float* r0 = (h > 0)  ? xp + (h-1)*64 : 0;
    const float* r1 = xp + h*64;
    const float* r2 = (h < 63) ? xp + (h+1)*64 : 0;
    float a0 = 0.f, a1 = 0.f, a2 = 0.f;
    float m0 = r0 ? r0[0] : 0.f;
    float m1 = r1[0];
    float m2 = r2 ? r2[0] : 0.f;
    float* ob = outp + (size_t)bh * 64 * 384 + c;
    #pragma unroll 4
    for (int w = 0; w < 64; w++) {
        float n0, n1, n2;
        if (w < 63) {
            n0 = r0 ? r0[w+1] : 0.f;
            n1 = r1[w+1];
            n2 = r2 ? r2[w+1] : 0.f;
        } else { n0 = n1 = n2 = 0.f; }
        float acc = bi
            + a0*k0 + m0*k1 + n0*k2
            + a1*k3 + m1*k4 + n1*k5
            + a2*k6 + m2*k7 + n2*k8;
        ob[(size_t)w * 384] = acc;
        a0 = m0; a1 = m1; a2 = m2;
        m0 = n0; m1 = n1; m2 = n2;
    }
}

// ================================================================ mma.sync split-bf16 GEMM
// C[128x128] tile of out[m,n] = sum_k A[m,k]*Wt[n,k] via
//   Ahi*Bhi + Ahi*Blo + Alo*Bhi  (fp32 register accumulators)
// MODE 0: lin  -> n<384 plain to o0 (xs), n>=384 silu to o1 (z)
// MODE 1: tok  -> gelu + modulation scalar -> o0
// MODE 2: out  -> plain bias -> o0
template<int MODE>
__global__ void __launch_bounds__(256) tgemm_k(
    const float* __restrict__ A, const float* __restrict__ Wt,
    const float* __restrict__ bias,
    float* __restrict__ o0, float* __restrict__ o1,
    const float* __restrict__ cp, const float* __restrict__ ap)
{
    extern __shared__ char sm[];
    // layout: A[2][128][128B], B[2][128][128B]  (hi|lo packed per row)
    char* sA = sm;
    char* sB = sm + 32768;

    const int t    = threadIdx.x;
    const int wid  = t >> 5;
    const int lane = t & 31;
    const int m0 = blockIdx.y * 128;
    const int n0 = blockIdx.x * 128;

    // ---------------- loader indexing
    const int arow = t >> 3;            // 0..31
    const int acg  = (t & 7) * 4;       // fp32 col within 32-chunk
    const float* Abase = A  + (size_t)(m0 + arow) * KDIM + acg;
    const float* Bbase = Wt + (size_t)(n0 + arow) * KDIM + acg;

    float4 pa[4], pb[4];
    #pragma unroll
    for (int r = 0; r < 4; r++) {
        pa[r] = *(const float4*)(Abase + (size_t)(r * 32) * KDIM);
        pb[r] = *(const float4*)(Bbase + (size_t)(r * 32) * KDIM);
    }
    #pragma unroll
    for (int r = 0; r < 4; r++) {
        st_split(sA, r * 32 + arow, acg, pa[r]);
        st_split(sB, r * 32 + arow, acg, pb[r]);
    }
    __syncthreads();

    // ---------------- compute setup
    const int wm = wid & 3;             // m slice (32 rows)
    const int wn = wid >> 2;            // n slice (64 cols)
    const uint32_t aS0 = smem_u32(sA);
    const uint32_t bS0 = smem_u32(sB);

    float acc[2][8][4];
    #pragma unroll
    for (int i = 0; i < 2; i++)
        #pragma unroll
        for (int j = 0; j < 8; j++)
            #pragma unroll
            for (int q = 0; q < 4; q++) acc[i][j][q] = 0.f;

    const int lrow = lane & 15;
    const int lkc  = (lane >> 4) << 3;   // 0 or 8 (element)

    const int NCH = KDIM / 32;           // 12
    for (int ch = 0; ch < NCH; ch++) {
        const int buf = ch & 1;
        if (ch + 1 < NCH) {
            const int kb = (ch + 1) * 32;
            #pragma unroll
            for (int r = 0; r < 4; r++) {
                pa[r] = *(const float4*)(Abase + (size_t)(r * 32) * KDIM + kb);
                pb[r] = *(const float4*)(Bbase + (size_t)(r * 32) * KDIM + kb);
            }
        }
        const uint32_t aS = aS0 + buf * 16384;
        const uint32_t bS = bS0 + buf * 16384;
        #pragma unroll
        for (int ks = 0; ks < 2; ks++) {
            const unsigned kc2 = (unsigned)(ks * 16 + lkc) * 2;
            uint32_t ahi[2][4], alo[2][4];
            #pragma unroll
            for (int mt = 0; mt < 2; mt++) {
                unsigned off = (unsigned)(wm * 32 + mt * 16 + lrow) * 128 + kc2;
                ldsm4(ahi[mt], aS + swz(off));
                ldsm4(alo[mt], aS + swz(off + 64));
            }
            uint32_t bhi[4][4], blo[4][4];
            #pragma unroll
            for (int ng = 0; ng < 4; ng++) {
                unsigned off = (unsigned)(wn * 64 + ng * 16 + lrow) * 128 + kc2;
                ldsm4(bhi[ng], bS + swz(off));
                ldsm4(blo[ng], bS + swz(off + 64));
            }
            #pragma unroll
            for (int mt = 0; mt < 2; mt++)
                #pragma unroll
                for (int ng = 0; ng < 4; ng++) {
                    mma16816(acc[mt][2*ng],   ahi[mt], bhi[ng][0], bhi[ng][2]);
                    mma16816(acc[mt][2*ng+1], ahi[mt], bhi[ng][1], bhi[ng][3]);
                    mma16816(acc[mt][2*ng],   ahi[mt], blo[ng][0], blo[ng][2]);
                    mma16816(acc[mt][2*ng+1], ahi[mt], blo[ng][1], blo[ng][3]);
                    mma16816(acc[mt][2*ng],   alo[mt], bhi[ng][0], bhi[ng][2]);
                    mma16816(acc[mt][2*ng+1], alo[mt], bhi[ng][1], bhi[ng][3]);
                }
        }
        if (ch + 1 < NCH) {
            char* dA = sA + (buf ^ 1) * 16384;
            char* dB = sB + (buf ^ 1) * 16384;
            #pragma unroll
            for (int r = 0; r < 4; r++) {
                st_split(dA, r * 32 + arow, acg, pa[r]);
                st_split(dB, r * 32 + arow, acg, pb[r]);
            }
            __syncthreads();
        }
    }

    // ---------------- epilogue
    const int qr = lane >> 2;        // 0..7
    const int qc = lane & 3;         // 0..3
    const int mbw = m0 + wm * 32;
    const int nbw = n0 + wn * 64;

    float cc0 = 0.f, css = 0.f;
    if (MODE == 1) {
        cc0 = cp[0];
        css = (1.0f + 0.5f * ap[0]) / (cc0 + 1e-8f);
    }

    #pragma unroll
    for (int mt = 0; mt < 2; mt++) {
        #pragma unroll
        for (int half = 0; half < 2; half++) {
            const int m = mbw + mt * 16 + qr + half * 8;
            float ee = 0.f;
            if (MODE == 1) {
                const float kp = 3.14159265358979323846f / 64.0f;
                int hh = (m >> 6) & 63, ww = m & 63;
                ee = kp * kp * (float)(hh * hh + ww * ww);
            }
            #pragma unroll
            for (int nt = 0; nt < 8; nt++) {
                const int n = nbw + nt * 8 + qc * 2;
                float v0 = acc[mt][nt][half * 2 + 0] + __ldg(bias + n);
                float v1 = acc[mt][nt][half * 2 + 1] + __ldg(bias + n + 1);
                if (MODE == 0) {
                    if (n0 >= 384) {
                        v0 *= 1.0f / (1.0f + __expf(-v0));
                        v1 *= 1.0f / (1.0f + __expf(-v1));
                        *(float2*)(o1 + (size_t)m * 384 + (n - 384)) = make_float2(v0, v1);
                    } else {
                        *(float2*)(o0 + (size_t)m * 384 + n) = make_float2(v0, v1);
                    }
                } else if (MODE == 1) {
                    float tg0 = 0.5f * v0 * (1.0f + erff(v0 * 0.70710678118654752f));
                    float tg1 = 0.5f * v1 * (1.0f + erff(v1 * 0.70710678118654752f));
                    float ct0 = cc0 * tg0, ct1 = cc0 * tg1;
                    float r0 = (__cosf(ct0) + __sinf(ct0) * css) * __expf(-ee * tg0);
                    float r1 = (__cosf(ct1) + __sinf(ct1) * css) * __expf(-ee * tg1);
                    *(float2*)(o0 + (size_t)m * 384 + n) = make_float2(r0, r1);
                } else {
                    *(float2*)(o0 + (size_t)m * 384 + n) = make_float2(v0, v1);
                }
            }
        }
    }
}

// ================================================================ batched 64-pt cosine transform
template<bool FWD, bool MOD>
__global__ void __launch_bounds__(256) dct_k(
    float* __restrict__ out, const float* __restrict__ X,
    const float* __restrict__ S, int ldRow)
{
    __shared__ float Ws[64][64];
    __shared__ float Xs[64][128];
    const int t  = threadIdx.x;
    const int bb = blockIdx.y;
    const int j0 = blockIdx.x << 7;
    for (int idx = t; idx < 4096; idx += 256) {
        int k = idx >> 6, i = idx & 63;
        Ws[k][i] = FWD ? g_W[(i << 6) + k] : g_W[(k << 6) + i];
    }
    const float* Xb = X + (size_t)bb * 64 * ldRow + j0;
    for (int f = t; f < 2048; f += 256) {
        int row = f >> 5, col = (f & 31) << 2;
        *(float4*)&Xs[row][col] = *(const float4*)(Xb + (size_t)row * ldRow + col);
    }
    __syncthreads();
    const int tx = t & 15, ty = t >> 4;
    const int i0 = ty << 2, jj = tx << 3;
    float acc[4][8];
    #pragma unroll
    for (int a = 0; a < 4; a++)
        #pragma unroll
        for (int b2 = 0; b2 < 8; b2++) acc[a][b2] = 0.f;
    #pragma unroll 8
    for (int k = 0; k < 64; k++) {
        float4 a  = *(const float4*)&Ws[k][i0];
        float4 b0 = *(const float4*)&Xs[k][jj];
        float4 b1 = *(const float4*)&Xs[k][jj + 4];
        float ar[4] = {a.x, a.y, a.z, a.w};
        float br[8] = {b0.x,b0.y,b0.z,b0.w,b1.x,b1.y,b1.z,b1.w};
        #pragma unroll
        for (int ii = 0; ii < 4; ii++)
            #pragma unroll
            for (int j = 0; j < 8; j++)
                acc[ii][j] = fmaf(ar[ii], br[j], acc[ii][j]);
    }
    float* ob = out + (size_t)bb * 64 * ldRow + j0;
    const float* sb = S + (size_t)bb * 64 * ldRow + j0;
    #pragma unroll
    for (int ii = 0; ii < 4; ii++) {
        size_t off = (size_t)(i0 + ii) * ldRow + jj;
        float4 r0 = make_float4(acc[ii][0],acc[ii][1],acc[ii][2],acc[ii][3]);
        float4 r1 = make_float4(acc[ii][4],acc[ii][5],acc[ii][6],acc[ii][7]);
        if (MOD) {
            float4 s0 = *(const float4*)(sb + off);
            float4 s1 = *(const float4*)(sb + off + 4);
            r0.x *= s0.x; r0.y *= s0.y; r0.z *= s0.z; r0.w *= s0.w;
            r1.x *= s1.x; r1.y *= s1.y; r1.z *= s1.z; r1.w *= s1.w;
        }
        *(float4*)(ob + off)     = r0;
        *(float4*)(ob + off + 4) = r1;
    }
}

// ================================================================ LayerNorm * silu(z)
__global__ void ln_silu_k(const float* __restrict__ xin, const float* __restrict__ zs,
                          const float* __restrict__ gam, const float* __restrict__ bet,
                          float* __restrict__ out)
{
    const int row = blockIdx.x;
    const int t = threadIdx.x;
    const float* xr = xin + (size_t)row * 384;
    float v0 = xr[t], v1 = xr[t + 128], v2 = xr[t + 256];
    float s = v0 + v1 + v2;
    __shared__ float r1[4], r2[4];
    #pragma unroll
    for (int o = 16; o; o >>= 1) s += __shfl_xor_sync(0xffffffffu, s, o);
    if ((t & 31) == 0) r1[t >> 5] = s;
    __syncthreads();
    float mu = (r1[0] + r1[1] + r1[2] + r1[3]) * (1.0f / 384.0f);
    float d0 = v0 - mu, d1 = v1 - mu, d2 = v2 - mu;
    float q = d0*d0 + d1*d1 + d2*d2;
    #pragma unroll
    for (int o = 16; o; o >>= 1) q += __shfl_xor_sync(0xffffffffu, q, o);
    if ((t & 31) == 0) r2[t >> 5] = q;
    __syncthreads();
    float var = (r2[0] + r2[1] + r2[2] + r2[3]) * (1.0f / 384.0f);
    float inv = rsqrtf(var + 1e-5f);
    const float* zr = zs + (size_t)row * 384;
    float* orow = out + (size_t)row * 384;
    orow[t]       = (d0 * inv * gam[t]       + bet[t])       * zr[t];
    orow[t + 128] = (d1 * inv * gam[t + 128] + bet[t + 128]) * zr[t + 128];
    orow[t + 256] = (d2 * inv * gam[t + 256] + bet[t + 256]) * zr[t + 256];
}

// ================================================================ launcher
#define TG_SMEM 65536

extern "C" void kernel_launch(void* const* d_in, const int* in_sizes, int n_in,
                              void* d_out, int out_size)
{
    const float* x     = (const float*)d_in[0];
    const float* freq  = (const float*)d_in[1];
    const float* dw_w  = (const float*)d_in[2];
    const float* dw_b  = (const float*)d_in[3];
    const float* lin_w = (const float*)d_in[4];
    const float* lin_b = (const float*)d_in[5];
    const float* tok_w = (const float*)d_in[6];
    const float* tok_b = (const float*)d_in[7];
    const float* ln_g  = (const float*)d_in[8];
    const float* ln_b  = (const float*)d_in[9];
    const float* out_w = (const float*)d_in[10];
    const float* out_b = (const float*)d_in[11];
    const float* cp    = (const float*)d_in[12];
    const float* ap    = (const float*)d_in[13];
    float* out = (float*)d_out;

    float *pxd, *pxs, *pz, *ps, *pf1, *pf2;
    cudaGetSymbolAddress((void**)&pxd, g_xd);
    cudaGetSymbolAddress((void**)&pxs, g_xs);
    cudaGetSymbolAddress((void**)&pz,  g_z);
    cudaGetSymbolAddress((void**)&ps,  g_s);
    cudaGetSymbolAddress((void**)&pf1, g_f1);
    cudaGetSymbolAddress((void**)&pf2, g_f2);

    cudaFuncSetAttribute((const void*)tgemm_k<0>, cudaFuncAttributeMaxDynamicSharedMemorySize, TG_SMEM);
    cudaFuncSetAttribute((const void*)tgemm_k<1>, cudaFuncAttributeMaxDynamicSharedMemorySize, TG_SMEM);
    cudaFuncSetAttribute((const void*)tgemm_k<2>, cudaFuncAttributeMaxDynamicSharedMemorySize, TG_SMEM);

    build_w_k<<<16, 256>>>();
    dwconv_k<<<1024, 384>>>(x, dw_w, dw_b, pxd);
    // xz = xd @ lin_w^T : xs + silu(z)
    tgemm_k<0><<<dim3(6, 512), 256, TG_SMEM>>>(pxd, lin_w, lin_b, pxs, pz, nullptr, nullptr);
    // s = modulation(gelu(freq @ tok_w^T))
    tgemm_k<1><<<dim3(3, 512), 256, TG_SMEM>>>(freq, tok_w, tok_b, ps, nullptr, cp, ap);
    // DCT over h
    dct_k<true,  false><<<dim3(192, 16),  256>>>(pf1, pxs, pf1, 24576);
    // DCT over w + modulate by s
    dct_k<true,  true ><<<dim3(3,  1024), 256>>>(pf2, pf1, ps, 384);
    // IDCT over n
    dct_k<false, false><<<dim3(192, 16),  256>>>(pf1, pf2, pf1, 24576);
    // IDCT over m
    dct_k<false, false><<<dim3(3,  1024), 256>>>(pf2, pf1, ps, 384);
    // layernorm * silu(z)
    ln_silu_k<<<65536, 128>>>(pf2, pz, ln_g, ln_b, pf1);
    // out = xo @ out_w^T + out_b
    tgemm_k<2><<<dim3(3, 512), 256, TG_SMEM>>>(pf1, out_w, out_b, out, nullptr, nullptr, nullptr);
}

// round 4
// speedup vs baseline: 1.4824x; 1.0409x over previous
#include <cuda_runtime.h>
#include <cuda_bf16.h>
#include <math.h>
#include <stdint.h>

#define KDIM 384
#define NEL 25165824   // 16*64*64*384

// fp32 buffers
static __device__ float g_xs[NEL];      // xs (pre-DCT)
static __device__ float g_z [NEL];      // silu(z)
static __device__ float g_s [NEL];      // modulation scalar
static __device__ float g_f1[NEL];
static __device__ float g_W[4096];      // 64x64 DCT-II matrix
// bf16 split buffers ([row][768]: hi 384 | lo 384), declared as float for size
static __device__ float g_xd[NEL];      // split conv output
static __device__ float g_fq[NEL];      // split freq_embed
static __device__ float g_f2[NEL];      // split LN output (also used as fp32 scratch in DCT chain)
static __device__ float g_wl[294912];   // split lin_w  (768 rows)
static __device__ float g_wt[147456];   // split tok_w  (384 rows)
static __device__ float g_wo[147456];   // split out_w  (384 rows)

// ================================================================ helpers
__device__ __forceinline__ uint32_t smem_u32(const void* p) {
    uint32_t a;
    asm("{ .reg .u64 t; cvta.to.shared.u64 t, %1; cvt.u32.u64 %0, t; }" : "=r"(a) : "l"(p));
    return a;
}
__device__ __forceinline__ void ldsm4(uint32_t (&r)[4], uint32_t addr) {
    asm volatile("ldmatrix.sync.aligned.m8n8.x4.shared.b16 {%0,%1,%2,%3}, [%4];"
                 : "=r"(r[0]), "=r"(r[1]), "=r"(r[2]), "=r"(r[3]) : "r"(addr));
}
__device__ __forceinline__ void mma16816(float (&d)[4], const uint32_t (&a)[4],
                                         uint32_t b0, uint32_t b1) {
    asm volatile(
        "mma.sync.aligned.m16n8k16.row.col.f32.bf16.bf16.f32 "
        "{%0,%1,%2,%3}, {%4,%5,%6,%7}, {%8,%9}, {%0,%1,%2,%3};"
        : "+f"(d[0]), "+f"(d[1]), "+f"(d[2]), "+f"(d[3])
        : "r"(a[0]), "r"(a[1]), "r"(a[2]), "r"(a[3]), "r"(b0), "r"(b1));
}
__device__ __forceinline__ unsigned swz(unsigned off) {
    return off ^ ((off >> 3) & 0x70);
}
__device__ __forceinline__ void cp16(uint32_t dst, const void* src) {
    asm volatile("cp.async.cg.shared.global [%0], [%1], 16;" :: "r"(dst), "l"(src) : "memory");
}
__device__ __forceinline__ void cp_commit() {
    asm volatile("cp.async.commit_group;" ::: "memory");
}
template<int N> __device__ __forceinline__ void cp_wait() {
    asm volatile("cp.async.wait_group %0;" :: "n"(N) : "memory");
}

// split one fp32 into hi/lo bf16
__device__ __forceinline__ void split2(float v, __nv_bfloat16& h, __nv_bfloat16& l) {
    h = __float2bfloat16(v);
    l = __float2bfloat16(v - __bfloat162float(h));
}

// ================================================================ build W
__global__ void build_w_k() {
    int i = blockIdx.x * 256 + threadIdx.x;
    int n = i >> 6, h = i & 63;
    float v = cosf((float)n * (((float)h + 0.5f) * (3.14159265358979323846f / 64.0f)))
            * 0.17677669529663687f;
    if (n == 0) v *= 0.70710678118654752f;
    g_W[i] = v;
}

// ================================================================ split fp32 [rows][384] -> bf16 [rows][768] (hi|lo)
__global__ void split_k(const float* __restrict__ src, __nv_bfloat16* __restrict__ dst, int n4) {
    int i = blockIdx.x * 256 + threadIdx.x;
    if (i >= n4) return;
    int row = i / 96;
    int col = (i - row * 96) * 4;
    float4 v = *(const float4*)(src + (size_t)row * 384 + col);
    __nv_bfloat16 h0,h1,h2,h3,l0,l1,l2,l3;
    split2(v.x,h0,l0); split2(v.y,h1,l1); split2(v.z,h2,l2); split2(v.w,h3,l3);
    __nv_bfloat16* d = dst + (size_t)row * 768 + col;
    d[0]=h0; d[1]=h1; d[2]=h2; d[3]=h3;
    d[384]=l0; d[385]=l1; d[386]=l2; d[387]=l3;
}

// ================================================================ depthwise conv 3x3, NCHW -> NHWC split bf16
__global__ void dwconv_k(const float* __restrict__ x, const float* __restrict__ w9,
                         const float* __restrict__ bias, __nv_bfloat16* __restrict__ outp)
{
    const int bh = blockIdx.x;
    const int c  = threadIdx.x;
    const int b  = bh >> 6, h = bh & 63;
    const float* xp = x + (size_t)(b * 384 + c) * 64 * 64;
    float k0 = w9[c*9+0], k1 = w9[c*9+1], k2 = w9[c*9+2];
    float k3 = w9[c*9+3], k4 = w9[c*9+4], k5 = w9[c*9+5];
    float k6 = w9[c*9+6], k7 = w9[c*9+7], k8 = w9[c*9+8];
    const float bi = bias[c];
    const float* r0 = (h > 0)  ? xp + (h-1)*64 : 0;
    const float* r1 = xp + h*64;
    const float* r2 = (h < 63) ? xp + (h+1)*64 : 0;
    float a0 = 0.f, a1 = 0.f, a2 = 0.f;
    float m0 = r0 ? r0[0] : 0.f;
    float m1 = r1[0];
    float m2 = r2 ? r2[0] : 0.f;
    __nv_bfloat16* ob = outp + (size_t)bh * 64 * 768 + c;
    #pragma unroll 4
    for (int w = 0; w < 64; w++) {
        float n0, n1, n2;
        if (w < 63) {
            n0 = r0 ? r0[w+1] : 0.f;
            n1 = r1[w+1];
            n2 = r2 ? r2[w+1] : 0.f;
        } else { n0 = n1 = n2 = 0.f; }
        float acc = bi
            + a0*k0 + m0*k1 + n0*k2
            + a1*k3 + m1*k4 + n1*k5
            + a2*k6 + m2*k7 + n2*k8;
        __nv_bfloat16 hi, lo; split2(acc, hi, lo);
        ob[(size_t)w * 768]       = hi;
        ob[(size_t)w * 768 + 384] = lo;
        a0 = m0; a1 = m1; a2 = m2;
        m0 = n0; m1 = n1; m2 = n2;
    }
}

// ================================================================ mma.sync split-bf16 GEMM (pre-split operands)
// A, Wt given as bf16 [row][768] (hi|lo). C tile 128x128.
// MODE 0: lin -> n<384 plain to o0 (xs), n>=384 silu to o1 (z)
// MODE 1: tok -> gelu + modulation scalar -> o0
// MODE 2: out -> plain bias -> o0
template<int MODE>
__global__ void __launch_bounds__(256) tgemm_k(
    const __nv_bfloat16* __restrict__ A, const __nv_bfloat16* __restrict__ Wt,
    const float* __restrict__ bias,
    float* __restrict__ o0, float* __restrict__ o1,
    const float* __restrict__ cp, const float* __restrict__ ap)
{
    extern __shared__ char sm[];
    const int t    = threadIdx.x;
    const int wid  = t >> 5;
    const int lane = t & 31;
    const int m0 = blockIdx.y * 128;
    const int n0 = blockIdx.x * 128;
    const uint32_t smemBase = smem_u32(sm);

    // ---------------- cp.async loader precompute: 2048 16B units/chunk, 8 per thread
    const __nv_bfloat16* srcP[8];
    uint32_t dstS[8];
    #pragma unroll
    for (int r = 0; r < 8; r++) {
        int u = t + 256 * r;
        int mat = u >> 10;
        int v = u & 1023;
        int row = v >> 3;
        int s7 = v & 7;
        const __nv_bfloat16* base = mat ? (Wt + (size_t)(n0 + row) * 768)
                                        : (A  + (size_t)(m0 + row) * 768);
        int col = (s7 < 4) ? s7 * 8 : 384 + (s7 - 4) * 8;
        srcP[r] = base + col;
        dstS[r] = smemBase + mat * 32768 + swz((unsigned)(row * 128 + s7 * 16));
    }

    // prologue: chunk 0 -> buf 0
    #pragma unroll
    for (int r = 0; r < 8; r++) cp16(dstS[r], srcP[r]);
    cp_commit();

    // ---------------- compute setup
    const int wm = wid & 3;
    const int wn = wid >> 2;
    float acc[2][8][4];
    #pragma unroll
    for (int i = 0; i < 2; i++)
        #pragma unroll
        for (int j = 0; j < 8; j++)
            #pragma unroll
            for (int q = 0; q < 4; q++) acc[i][j][q] = 0.f;

    const int lrow = lane & 15;
    const int lkc  = (lane >> 4) << 3;

    const int NCH = KDIM / 32;   // 12
    for (int ch = 0; ch < NCH; ch++) {
        const int buf = ch & 1;
        if (ch + 1 < NCH) {
            const int nb = (ch + 1) & 1;
            #pragma unroll
            for (int r = 0; r < 8; r++)
                cp16(dstS[r] + nb * 16384, srcP[r] + (ch + 1) * 32);
            cp_commit();
            cp_wait<1>();
        } else {
            cp_wait<0>();
        }
        __syncthreads();

        const uint32_t aS = smemBase + buf * 16384;
        const uint32_t bS = smemBase + 32768 + buf * 16384;
        #pragma unroll
        for (int ks = 0; ks < 2; ks++) {
            const unsigned kc2 = (unsigned)(ks * 16 + lkc) * 2;
            uint32_t ahi[2][4], alo[2][4];
            #pragma unroll
            for (int mt = 0; mt < 2; mt++) {
                unsigned off = (unsigned)(wm * 32 + mt * 16 + lrow) * 128 + kc2;
                ldsm4(ahi[mt], aS + swz(off));
                ldsm4(alo[mt], aS + swz(off + 64));
            }
            uint32_t bhi[4][4], blo[4][4];
            #pragma unroll
            for (int ng = 0; ng < 4; ng++) {
                unsigned off = (unsigned)(wn * 64 + ng * 16 + lrow) * 128 + kc2;
                ldsm4(bhi[ng], bS + swz(off));
                ldsm4(blo[ng], bS + swz(off + 64));
            }
            #pragma unroll
            for (int mt = 0; mt < 2; mt++)
                #pragma unroll
                for (int ng = 0; ng < 4; ng++) {
                    mma16816(acc[mt][2*ng],   ahi[mt], bhi[ng][0], bhi[ng][2]);
                    mma16816(acc[mt][2*ng+1], ahi[mt], bhi[ng][1], bhi[ng][3]);
                    mma16816(acc[mt][2*ng],   ahi[mt], blo[ng][0], blo[ng][2]);
                    mma16816(acc[mt][2*ng+1], ahi[mt], blo[ng][1], blo[ng][3]);
                    mma16816(acc[mt][2*ng],   alo[mt], bhi[ng][0], bhi[ng][2]);
                    mma16816(acc[mt][2*ng+1], alo[mt], bhi[ng][1], bhi[ng][3]);
                }
        }
        __syncthreads();
    }

    // ---------------- epilogue
    const int qr = lane >> 2;
    const int qc = lane & 3;
    const int mbw = m0 + wm * 32;
    const int nbw = n0 + wn * 64;

    float cc0 = 0.f, css = 0.f;
    if (MODE == 1) {
        cc0 = cp[0];
        css = (1.0f + 0.5f * ap[0]) / (cc0 + 1e-8f);
    }

    #pragma unroll
    for (int mt = 0; mt < 2; mt++) {
        #pragma unroll
        for (int half = 0; half < 2; half++) {
            const int m = mbw + mt * 16 + qr + half * 8;
            float ee = 0.f;
            if (MODE == 1) {
                const float kp = 3.14159265358979323846f / 64.0f;
                int hh = (m >> 6) & 63, ww = m & 63;
                ee = kp * kp * (float)(hh * hh + ww * ww);
            }
            #pragma unroll
            for (int nt = 0; nt < 8; nt++) {
                const int n = nbw + nt * 8 + qc * 2;
                float v0 = acc[mt][nt][half * 2 + 0] + __ldg(bias + n);
                float v1 = acc[mt][nt][half * 2 + 1] + __ldg(bias + n + 1);
                if (MODE == 0) {
                    if (n0 >= 384) {
                        v0 *= 1.0f / (1.0f + __expf(-v0));
                        v1 *= 1.0f / (1.0f + __expf(-v1));
                        *(float2*)(o1 + (size_t)m * 384 + (n - 384)) = make_float2(v0, v1);
                    } else {
                        *(float2*)(o0 + (size_t)m * 384 + n) = make_float2(v0, v1);
                    }
                } else if (MODE == 1) {
                    float tg0 = 0.5f * v0 * (1.0f + erff(v0 * 0.70710678118654752f));
                    float tg1 = 0.5f * v1 * (1.0f + erff(v1 * 0.70710678118654752f));
                    float ct0 = cc0 * tg0, ct1 = cc0 * tg1;
                    float r0 = (__cosf(ct0) + __sinf(ct0) * css) * __expf(-ee * tg0);
                    float r1 = (__cosf(ct1) + __sinf(ct1) * css) * __expf(-ee * tg1);
                    *(float2*)(o0 + (size_t)m * 384 + n) = make_float2(r0, r1);
                } else {
                    *(float2*)(o0 + (size_t)m * 384 + n) = make_float2(v0, v1);
                }
            }
        }
    }
}

// ================================================================ batched 64-pt cosine transform
template<bool FWD, bool MOD>
__global__ void __launch_bounds__(256) dct_k(
    float* __restrict__ out, const float* __restrict__ X,
    const float* __restrict__ S, int ldRow)
{
    __shared__ float Ws[64][64];
    __shared__ float Xs[64][128];
    const int t  = threadIdx.x;
    const int bb = blockIdx.y;
    const int j0 = blockIdx.x << 7;
    for (int idx = t; idx < 4096; idx += 256) {
        int k = idx >> 6, i = idx & 63;
        Ws[k][i] = FWD ? g_W[(i << 6) + k] : g_W[(k << 6) + i];
    }
    const float* Xb = X + (size_t)bb * 64 * ldRow + j0;
    for (int f = t; f < 2048; f += 256) {
        int row = f >> 5, col = (f & 31) << 2;
        *(float4*)&Xs[row][col] = *(const float4*)(Xb + (size_t)row * ldRow + col);
    }
    __syncthreads();
    const int tx = t & 15, ty = t >> 4;
    const int i0 = ty << 2, jj = tx << 3;
    float acc[4][8];
    #pragma unroll
    for (int a = 0; a < 4; a++)
        #pragma unroll
        for (int b2 = 0; b2 < 8; b2++) acc[a][b2] = 0.f;
    #pragma unroll 8
    for (int k = 0; k < 64; k++) {
        float4 a  = *(const float4*)&Ws[k][i0];
        float4 b0 = *(const float4*)&Xs[k][jj];
        float4 b1 = *(const float4*)&Xs[k][jj + 4];
        float ar[4] = {a.x, a.y, a.z, a.w};
        float br[8] = {b0.x,b0.y,b0.z,b0.w,b1.x,b1.y,b1.z,b1.w};
        #pragma unroll
        for (int ii = 0; ii < 4; ii++)
            #pragma unroll
            for (int j = 0; j < 8; j++)
                acc[ii][j] = fmaf(ar[ii], br[j], acc[ii][j]);
    }
    float* ob = out + (size_t)bb * 64 * ldRow + j0;
    const float* sb = S + (size_t)bb * 64 * ldRow + j0;
    #pragma unroll
    for (int ii = 0; ii < 4; ii++) {
        size_t off = (size_t)(i0 + ii) * ldRow + jj;
        float4 r0 = make_float4(acc[ii][0],acc[ii][1],acc[ii][2],acc[ii][3]);
        float4 r1 = make_float4(acc[ii][4],acc[ii][5],acc[ii][6],acc[ii][7]);
        if (MOD) {
            float4 s0 = *(const float4*)(sb + off);
            float4 s1 = *(const float4*)(sb + off + 4);
            r0.x *= s0.x; r0.y *= s0.y; r0.z *= s0.z; r0.w *= s0.w;
            r1.x *= s1.x; r1.y *= s1.y; r1.z *= s1.z; r1.w *= s1.w;
        }
        *(float4*)(ob + off)     = r0;
        *(float4*)(ob + off + 4) = r1;
    }
}

// ================================================================ fused IDCT(w) + LayerNorm + silu-gate + bf16 split
// block bb = b*64+h: in X[(bb)][64 m][384 c], contract m with W[m][w];
// then LN over c per w-row, multiply silu(z), write split bf16 [pixel][768].
#define DL_SMEM ((4096 + 2*64*392) * 4)
__global__ void __launch_bounds__(256) dct_ln_k(
    const float* __restrict__ X, const float* __restrict__ z,
    const float* __restrict__ gam, const float* __restrict__ bet,
    __nv_bfloat16* __restrict__ dst)
{
    extern __shared__ float s[];
    float* Ws = s;                 // 4096: Ws[m*64+w] = W[m][w]
    float* Xs = s + 4096;          // 64 x 392
    float* Os = s + 4096 + 64*392; // 64 x 392
    const int t = threadIdx.x;
    const int bb = blockIdx.x;

    for (int idx = t; idx < 4096; idx += 256) Ws[idx] = g_W[idx];
    const float* Xb = X + (size_t)bb * 24576;
    for (int f = t; f < 6144; f += 256) {
        int row = f / 96, col = (f - row * 96) * 4;
        *(float4*)&Xs[row * 392 + col] = *(const float4*)(Xb + (size_t)row * 384 + col);
    }
    __syncthreads();

    // compute: thread -> 2 w-rows (wpair), 48 c each (c = cg + 8*jj)
    const int wpair = t >> 3;      // 0..31
    const int cg = t & 7;          // 0..7
    const int w0 = wpair * 2;
    #pragma unroll
    for (int jb = 0; jb < 4; jb++) {
        float a0[12], a1[12];
        #pragma unroll
        for (int j = 0; j < 12; j++) { a0[j] = 0.f; a1[j] = 0.f; }
        #pragma unroll 4
        for (int m = 0; m < 64; m++) {
            float wv0 = Ws[m * 64 + w0];
            float wv1 = Ws[m * 64 + w0 + 1];
            const float* xr = &Xs[m * 392 + cg + 8 * (jb * 12)];
            #pragma unroll
            for (int j = 0; j < 12; j++) {
                float xv = xr[8 * j];
                a0[j] = fmaf(wv0, xv, a0[j]);
                a1[j] = fmaf(wv1, xv, a1[j]);
            }
        }
        #pragma unroll
        for (int j = 0; j < 12; j++) {
            int c = cg + 8 * (jb * 12 + j);
            Os[w0 * 392 + c]       = a0[j];
            Os[(w0 + 1) * 392 + c] = a1[j];
        }
    }
    __syncthreads();

    // LN per w-row (8 warps x 8 rows), x silu(z), split-store
    const int warp = t >> 5, lane = t & 31;
    float gv[12], bv[12];
    #pragma unroll
    for (int k = 0; k < 12; k++) { gv[k] = gam[lane + 32*k]; bv[k] = bet[lane + 32*k]; }
    for (int w = warp; w < 64; w += 8) {
        float vals[12], sum = 0.f;
        #pragma unroll
        for (int k = 0; k < 12; k++) { vals[k] = Os[w * 392 + lane + 32*k]; sum += vals[k]; }
        #pragma unroll
        for (int o = 16; o; o >>= 1) sum += __shfl_xor_sync(0xffffffffu, sum, o);
        float mu = sum * (1.0f / 384.0f);
        float q = 0.f;
        #pragma unroll
        for (int k = 0; k < 12; k++) { float d = vals[k] - mu; q = fmaf(d, d, q); }
        #pragma unroll
        for (int o = 16; o; o >>= 1) q += __shfl_xor_sync(0xffffffffu, q, o);
        float inv = rsqrtf(q * (1.0f / 384.0f) + 1e-5f);
        const size_t pixel = (size_t)bb * 64 + w;
        const float* zr = z + pixel * 384;
        __nv_bfloat16* dr = dst + pixel * 768;
        #pragma unroll
        for (int k = 0; k < 12; k++) {
            int c = lane + 32*k;
            float o = ((vals[k] - mu) * inv * gv[k] + bv[k]) * zr[c];
            __nv_bfloat16 hi, lo; split2(o, hi, lo);
            dr[c] = hi; dr[384 + c] = lo;
        }
    }
}

// ================================================================ launcher
#define TG_SMEM 65536

extern "C" void kernel_launch(void* const* d_in, const int* in_sizes, int n_in,
                              void* d_out, int out_size)
{
    const float* x     = (const float*)d_in[0];
    const float* freq  = (const float*)d_in[1];
    const float* dw_w  = (const float*)d_in[2];
    const float* dw_b  = (const float*)d_in[3];
    const float* lin_w = (const float*)d_in[4];
    const float* lin_b = (const float*)d_in[5];
    const float* tok_w = (const float*)d_in[6];
    const float* tok_b = (const float*)d_in[7];
    const float* ln_g  = (const float*)d_in[8];
    const float* ln_b  = (const float*)d_in[9];
    const float* out_w = (const float*)d_in[10];
    const float* out_b = (const float*)d_in[11];
    const float* cp    = (const float*)d_in[12];
    const float* ap    = (const float*)d_in[13];
    float* out = (float*)d_out;

    float *pxs, *pz, *ps, *pf1;
    __nv_bfloat16 *pxd, *pfq, *pf2, *pwl, *pwt, *pwo;
    cudaGetSymbolAddress((void**)&pxs, g_xs);
    cudaGetSymbolAddress((void**)&pz,  g_z);
    cudaGetSymbolAddress((void**)&ps,  g_s);
    cudaGetSymbolAddress((void**)&pf1, g_f1);
    cudaGetSymbolAddress((void**)&pxd, g_xd);
    cudaGetSymbolAddress((void**)&pfq, g_fq);
    cudaGetSymbolAddress((void**)&pf2, g_f2);
    cudaGetSymbolAddress((void**)&pwl, g_wl);
    cudaGetSymbolAddress((void**)&pwt, g_wt);
    cudaGetSymbolAddress((void**)&pwo, g_wo);

    cudaFuncSetAttribute((const void*)tgemm_k<0>, cudaFuncAttributeMaxDynamicSharedMemorySize, TG_SMEM);
    cudaFuncSetAttribute((const void*)tgemm_k<1>, cudaFuncAttributeMaxDynamicSharedMemorySize, TG_SMEM);
    cudaFuncSetAttribute((const void*)tgemm_k<2>, cudaFuncAttributeMaxDynamicSharedMemorySize, TG_SMEM);
    cudaFuncSetAttribute((const void*)dct_ln_k,   cudaFuncAttributeMaxDynamicSharedMemorySize, DL_SMEM);

    build_w_k<<<16, 256>>>();
    // one-shot weight splits + freq split
    split_k<<<(768*96 + 255)/256, 256>>>(lin_w, pwl, 768*96);
    split_k<<<(384*96 + 255)/256, 256>>>(tok_w, pwt, 384*96);
    split_k<<<(384*96 + 255)/256, 256>>>(out_w, pwo, 384*96);
    split_k<<<(65536*96 + 255)/256, 256>>>(freq, pfq, 65536*96);
    // conv -> split bf16
    dwconv_k<<<1024, 384>>>(x, dw_w, dw_b, pxd);
    // xz = xd @ lin_w^T : xs + silu(z)
    tgemm_k<0><<<dim3(6, 512), 256, TG_SMEM>>>(pxd, pwl, lin_b, pxs, pz, nullptr, nullptr);
    // s = modulation(gelu(freq @ tok_w^T))
    tgemm_k<1><<<dim3(3, 512), 256, TG_SMEM>>>(pfq, pwt, tok_b, ps, nullptr, cp, ap);
    // DCT over h
    dct_k<true,  false><<<dim3(192, 16),  256>>>(pf1, pxs, pf1, 24576);
    // DCT over w + modulate by s
    dct_k<true,  true ><<<dim3(3,  1024), 256>>>((float*)pf2, pf1, ps, 384);
    // IDCT over n
    dct_k<false, false><<<dim3(192, 16),  256>>>(pf1, (float*)pf2, pf1, 24576);
    // fused IDCT over m + LayerNorm + silu-gate -> split bf16
    dct_ln_k<<<1024, 256, DL_SMEM>>>(pf1, pz, ln_g, ln_b, pf2);
    // out = xo @ out_w^T + out_b
    tgemm_k<2><<<dim3(3, 512), 256, TG_SMEM>>>(pf2, pwo, out_b, out, nullptr, nullptr, nullptr);
}

// round 5
// speedup vs baseline: 1.7626x; 1.1891x over previous
#include <cuda_runtime.h>
#include <cuda_bf16.h>
#include <math.h>
#include <stdint.h>

#define KDIM 384
#define NEL 25165824   // 16*64*64*384

// fp32 buffers
static __device__ float g_xs[NEL];      // xs (pre-DCT)
static __device__ float g_z [NEL];      // silu(z)
static __device__ float g_s [NEL];      // modulation scalar
static __device__ float g_f1[NEL];
static __device__ float g_W[4096];      // 64x64 DCT-II matrix (fp32, for dct_ln)
// bf16 split W planes: [orient][plane hi/lo][64][72]
static __device__ __nv_bfloat16 g_Wsp[2][2][64][72];
// bf16 split buffers ([row][768]: hi 384 | lo 384), declared as float for size
static __device__ float g_xd[NEL];      // split conv output
static __device__ float g_fq[NEL];      // split freq_embed
static __device__ float g_f2[NEL];      // split LN output / fp32 scratch
static __device__ float g_wl[294912];   // split lin_w  (768 rows)
static __device__ float g_wt[147456];   // split tok_w  (384 rows)
static __device__ float g_wo[147456];   // split out_w  (384 rows)

// ================================================================ helpers
__device__ __forceinline__ uint32_t smem_u32(const void* p) {
    uint32_t a;
    asm("{ .reg .u64 t; cvta.to.shared.u64 t, %1; cvt.u32.u64 %0, t; }" : "=r"(a) : "l"(p));
    return a;
}
__device__ __forceinline__ void ldsm4(uint32_t (&r)[4], uint32_t addr) {
    asm volatile("ldmatrix.sync.aligned.m8n8.x4.shared.b16 {%0,%1,%2,%3}, [%4];"
                 : "=r"(r[0]), "=r"(r[1]), "=r"(r[2]), "=r"(r[3]) : "r"(addr));
}
__device__ __forceinline__ void ldsm4t(uint32_t (&r)[4], uint32_t addr) {
    asm volatile("ldmatrix.sync.aligned.m8n8.x4.trans.shared.b16 {%0,%1,%2,%3}, [%4];"
                 : "=r"(r[0]), "=r"(r[1]), "=r"(r[2]), "=r"(r[3]) : "r"(addr));
}
__device__ __forceinline__ void mma16816(float (&d)[4], const uint32_t (&a)[4],
                                         uint32_t b0, uint32_t b1) {
    asm volatile(
        "mma.sync.aligned.m16n8k16.row.col.f32.bf16.bf16.f32 "
        "{%0,%1,%2,%3}, {%4,%5,%6,%7}, {%8,%9}, {%0,%1,%2,%3};"
        : "+f"(d[0]), "+f"(d[1]), "+f"(d[2]), "+f"(d[3])
        : "r"(a[0]), "r"(a[1]), "r"(a[2]), "r"(a[3]), "r"(b0), "r"(b1));
}
__device__ __forceinline__ unsigned swz(unsigned off) {
    return off ^ ((off >> 3) & 0x70);
}
__device__ __forceinline__ void cp16(uint32_t dst, const void* src) {
    asm volatile("cp.async.cg.shared.global [%0], [%1], 16;" :: "r"(dst), "l"(src) : "memory");
}
__device__ __forceinline__ void cp_commit() {
    asm volatile("cp.async.commit_group;" ::: "memory");
}
template<int N> __device__ __forceinline__ void cp_wait() {
    asm volatile("cp.async.wait_group %0;" :: "n"(N) : "memory");
}
__device__ __forceinline__ void split2(float v, __nv_bfloat16& h, __nv_bfloat16& l) {
    h = __float2bfloat16(v);
    l = __float2bfloat16(v - __bfloat162float(h));
}

// ================================================================ build W (fp32 + split planes, both orientations)
__global__ void build_w_k() {
    int i = blockIdx.x * 256 + threadIdx.x;
    int n = i >> 6, h = i & 63;
    float v = cosf((float)n * (((float)h + 0.5f) * (3.14159265358979323846f / 64.0f)))
            * 0.17677669529663687f;
    if (n == 0) v *= 0.70710678118654752f;
    g_W[i] = v;
    __nv_bfloat16 hi, lo; split2(v, hi, lo);
    // FWD: Weff[i,k] = W[n=i][h=k]
    g_Wsp[0][0][n][h] = hi;
    g_Wsp[0][1][n][h] = lo;
    // BWD: Weff[i,k] = W[k][i] -> element (n,h) goes to [i=h][k=n]
    g_Wsp[1][0][h][n] = hi;
    g_Wsp[1][1][h][n] = lo;
}

// ================================================================ split fp32 [rows][384] -> bf16 [rows][768]
__global__ void split_k(const float* __restrict__ src, __nv_bfloat16* __restrict__ dst, int n4) {
    int i = blockIdx.x * 256 + threadIdx.x;
    if (i >= n4) return;
    int row = i / 96;
    int col = (i - row * 96) * 4;
    float4 v = *(const float4*)(src + (size_t)row * 384 + col);
    __nv_bfloat16 h0,h1,h2,h3,l0,l1,l2,l3;
    split2(v.x,h0,l0); split2(v.y,h1,l1); split2(v.z,h2,l2); split2(v.w,h3,l3);
    __nv_bfloat16* d = dst + (size_t)row * 768 + col;
    d[0]=h0; d[1]=h1; d[2]=h2; d[3]=h3;
    d[384]=l0; d[385]=l1; d[386]=l2; d[387]=l3;
}

// ================================================================ depthwise conv 3x3, NCHW -> NHWC split bf16
__global__ void dwconv_k(const float* __restrict__ x, const float* __restrict__ w9,
                         const float* __restrict__ bias, __nv_bfloat16* __restrict__ outp)
{
    const int bh = blockIdx.x;
    const int c  = threadIdx.x;
    const int b  = bh >> 6, h = bh & 63;
    const float* xp = x + (size_t)(b * 384 + c) * 64 * 64;
    float k0 = w9[c*9+0], k1 = w9[c*9+1], k2 = w9[c*9+2];
    float k3 = w9[c*9+3], k4 = w9[c*9+4], k5 = w9[c*9+5];
    float k6 = w9[c*9+6], k7 = w9[c*9+7], k8 = w9[c*9+8];
    const float bi = bias[c];
    const float* r0 = (h > 0)  ? xp + (h-1)*64 : 0;
    const float* r1 = xp + h*64;
    const float* r2 = (h < 63) ? xp + (h+1)*64 : 0;
    float a0 = 0.f, a1 = 0.f, a2 = 0.f;
    float m0 = r0 ? r0[0] : 0.f;
    float m1 = r1[0];
    float m2 = r2 ? r2[0] : 0.f;
    __nv_bfloat16* ob = outp + (size_t)bh * 64 * 768 + c;
    #pragma unroll 4
    for (int w = 0; w < 64; w++) {
        float n0, n1, n2;
        if (w < 63) {
            n0 = r0 ? r0[w+1] : 0.f;
            n1 = r1[w+1];
            n2 = r2 ? r2[w+1] : 0.f;
        } else { n0 = n1 = n2 = 0.f; }
        float acc = bi
            + a0*k0 + m0*k1 + n0*k2
            + a1*k3 + m1*k4 + n1*k5
            + a2*k6 + m2*k7 + n2*k8;
        __nv_bfloat16 hi, lo; split2(acc, hi, lo);
        ob[(size_t)w * 768]       = hi;
        ob[(size_t)w * 768 + 384] = lo;
        a0 = m0; a1 = m1; a2 = m2;
        m0 = n0; m1 = n1; m2 = n2;
    }
}

// ================================================================ mma.sync split-bf16 GEMM (pre-split operands)
template<int MODE>
__global__ void __launch_bounds__(256) tgemm_k(
    const __nv_bfloat16* __restrict__ A, const __nv_bfloat16* __restrict__ Wt,
    const float* __restrict__ bias,
    float* __restrict__ o0, float* __restrict__ o1,
    const float* __restrict__ cp, const float* __restrict__ ap)
{
    extern __shared__ char sm[];
    const int t    = threadIdx.x;
    const int wid  = t >> 5;
    const int lane = t & 31;
    const int m0 = blockIdx.y * 128;
    const int n0 = blockIdx.x * 128;
    const uint32_t smemBase = smem_u32(sm);

    const __nv_bfloat16* srcP[8];
    uint32_t dstS[8];
    #pragma unroll
    for (int r = 0; r < 8; r++) {
        int u = t + 256 * r;
        int mat = u >> 10;
        int v = u & 1023;
        int row = v >> 3;
        int s7 = v & 7;
        const __nv_bfloat16* base = mat ? (Wt + (size_t)(n0 + row) * 768)
                                        : (A  + (size_t)(m0 + row) * 768);
        int col = (s7 < 4) ? s7 * 8 : 384 + (s7 - 4) * 8;
        srcP[r] = base + col;
        dstS[r] = smemBase + mat * 32768 + swz((unsigned)(row * 128 + s7 * 16));
    }

    #pragma unroll
    for (int r = 0; r < 8; r++) cp16(dstS[r], srcP[r]);
    cp_commit();

    const int wm = wid & 3;
    const int wn = wid >> 2;
    float acc[2][8][4];
    #pragma unroll
    for (int i = 0; i < 2; i++)
        #pragma unroll
        for (int j = 0; j < 8; j++)
            #pragma unroll
            for (int q = 0; q < 4; q++) acc[i][j][q] = 0.f;

    const int lrow = lane & 15;
    const int lkc  = (lane >> 4) << 3;

    const int NCH = KDIM / 32;   // 12
    for (int ch = 0; ch < NCH; ch++) {
        const int buf = ch & 1;
        if (ch + 1 < NCH) {
            const int nb = (ch + 1) & 1;
            #pragma unroll
            for (int r = 0; r < 8; r++)
                cp16(dstS[r] + nb * 16384, srcP[r] + (ch + 1) * 32);
            cp_commit();
            cp_wait<1>();
        } else {
            cp_wait<0>();
        }
        __syncthreads();

        const uint32_t aS = smemBase + buf * 16384;
        const uint32_t bS = smemBase + 32768 + buf * 16384;
        #pragma unroll
        for (int ks = 0; ks < 2; ks++) {
            const unsigned kc2 = (unsigned)(ks * 16 + lkc) * 2;
            uint32_t ahi[2][4], alo[2][4];
            #pragma unroll
            for (int mt = 0; mt < 2; mt++) {
                unsigned off = (unsigned)(wm * 32 + mt * 16 + lrow) * 128 + kc2;
                ldsm4(ahi[mt], aS + swz(off));
                ldsm4(alo[mt], aS + swz(off + 64));
            }
            uint32_t bhi[4][4], blo[4][4];
            #pragma unroll
            for (int ng = 0; ng < 4; ng++) {
                unsigned off = (unsigned)(wn * 64 + ng * 16 + lrow) * 128 + kc2;
                ldsm4(bhi[ng], bS + swz(off));
                ldsm4(blo[ng], bS + swz(off + 64));
            }
            #pragma unroll
            for (int mt = 0; mt < 2; mt++)
                #pragma unroll
                for (int ng = 0; ng < 4; ng++) {
                    mma16816(acc[mt][2*ng],   ahi[mt], bhi[ng][0], bhi[ng][2]);
                    mma16816(acc[mt][2*ng+1], ahi[mt], bhi[ng][1], bhi[ng][3]);
                    mma16816(acc[mt][2*ng],   ahi[mt], blo[ng][0], blo[ng][2]);
                    mma16816(acc[mt][2*ng+1], ahi[mt], blo[ng][1], blo[ng][3]);
                    mma16816(acc[mt][2*ng],   alo[mt], bhi[ng][0], bhi[ng][2]);
                    mma16816(acc[mt][2*ng+1], alo[mt], bhi[ng][1], bhi[ng][3]);
                }
        }
        __syncthreads();
    }

    const int qr = lane >> 2;
    const int qc = lane & 3;
    const int mbw = m0 + wm * 32;
    const int nbw = n0 + wn * 64;

    float cc0 = 0.f, css = 0.f;
    if (MODE == 1) {
        cc0 = cp[0];
        css = (1.0f + 0.5f * ap[0]) / (cc0 + 1e-8f);
    }

    #pragma unroll
    for (int mt = 0; mt < 2; mt++) {
        #pragma unroll
        for (int half = 0; half < 2; half++) {
            const int m = mbw + mt * 16 + qr + half * 8;
            float ee = 0.f;
            if (MODE == 1) {
                const float kp = 3.14159265358979323846f / 64.0f;
                int hh = (m >> 6) & 63, ww = m & 63;
                ee = kp * kp * (float)(hh * hh + ww * ww);
            }
            #pragma unroll
            for (int nt = 0; nt < 8; nt++) {
                const int n = nbw + nt * 8 + qc * 2;
                float v0 = acc[mt][nt][half * 2 + 0] + __ldg(bias + n);
                float v1 = acc[mt][nt][half * 2 + 1] + __ldg(bias + n + 1);
                if (MODE == 0) {
                    if (n0 >= 384) {
                        v0 *= 1.0f / (1.0f + __expf(-v0));
                        v1 *= 1.0f / (1.0f + __expf(-v1));
                        *(float2*)(o1 + (size_t)m * 384 + (n - 384)) = make_float2(v0, v1);
                    } else {
                        *(float2*)(o0 + (size_t)m * 384 + n) = make_float2(v0, v1);
                    }
                } else if (MODE == 1) {
                    float tg0 = 0.5f * v0 * (1.0f + erff(v0 * 0.70710678118654752f));
                    float tg1 = 0.5f * v1 * (1.0f + erff(v1 * 0.70710678118654752f));
                    float ct0 = cc0 * tg0, ct1 = cc0 * tg1;
                    float r0 = (__cosf(ct0) + __sinf(ct0) * css) * __expf(-ee * tg0);
                    float r1 = (__cosf(ct1) + __sinf(ct1) * css) * __expf(-ee * tg1);
                    *(float2*)(o0 + (size_t)m * 384 + n) = make_float2(r0, r1);
                } else {
                    *(float2*)(o0 + (size_t)m * 384 + n) = make_float2(v0, v1);
                }
            }
        }
    }
}

// ================================================================ tensorized 64-pt cosine transform (split bf16)
// out[bb,i,j] = sum_k Weff[i,k] * X[bb,k,j], 64 rows, 128 cols per block
// smem: Xhi[64][136], Xlo[64][136], Whi[64][72], Wlo[64][72]
#define DT_SMEM (17408*2 + 9216*2)
template<bool FWD, bool MOD>
__global__ void __launch_bounds__(256) dctT_k(
    float* __restrict__ out, const float* __restrict__ X,
    const float* __restrict__ S, int ldRow)
{
    extern __shared__ char ds[];
    __nv_bfloat16* sXhi = (__nv_bfloat16*)ds;
    __nv_bfloat16* sXlo = (__nv_bfloat16*)(ds + 17408);
    __nv_bfloat16* sWp  = (__nv_bfloat16*)(ds + 34816);
    const int t = threadIdx.x;
    const int bb = blockIdx.y;
    const int j0 = blockIdx.x << 7;

    // copy W planes (hi then lo, contiguous, layout-identical)
    {
        const uint4* src = (const uint4*)&g_Wsp[FWD ? 0 : 1][0][0][0];
        uint4* dst = (uint4*)sWp;
        for (int u = t; u < 1152; u += 256) dst[u] = src[u];
    }
    // load X slab, split to hi/lo
    const float* Xb = X + (size_t)bb * 64 * ldRow + j0;
    #pragma unroll
    for (int it = 0; it < 8; it++) {
        int idx = t + 256 * it;
        int row = idx >> 5, c4 = (idx & 31) << 2;
        float4 v = *(const float4*)(Xb + (size_t)row * ldRow + c4);
        __nv_bfloat16 h0,h1,h2,h3,l0,l1,l2,l3;
        split2(v.x,h0,l0); split2(v.y,h1,l1); split2(v.z,h2,l2); split2(v.w,h3,l3);
        unsigned hw0 = ((unsigned)__bfloat16_as_ushort(h1) << 16) | __bfloat16_as_ushort(h0);
        unsigned hw1 = ((unsigned)__bfloat16_as_ushort(h3) << 16) | __bfloat16_as_ushort(h2);
        unsigned lw0 = ((unsigned)__bfloat16_as_ushort(l1) << 16) | __bfloat16_as_ushort(l0);
        unsigned lw1 = ((unsigned)__bfloat16_as_ushort(l3) << 16) | __bfloat16_as_ushort(l2);
        *(uint2*)(sXhi + row * 136 + c4) = make_uint2(hw0, hw1);
        *(uint2*)(sXlo + row * 136 + c4) = make_uint2(lw0, lw1);
    }
    __syncthreads();

    const int wid = t >> 5, lane = t & 31;
    const int wm = wid & 1, wn = wid >> 1;
    const uint32_t xhiB = smem_u32(sXhi), xloB = smem_u32(sXlo);
    const uint32_t whiB = smem_u32(sWp),  wloB = whiB + 9216;

    float acc[2][4][4];
    #pragma unroll
    for (int i = 0; i < 2; i++)
        #pragma unroll
        for (int j = 0; j < 4; j++)
            #pragma unroll
            for (int q = 0; q < 4; q++) acc[i][j][q] = 0.f;

    const int lr = lane & 15, lh = lane >> 4;
    #pragma unroll
    for (int ks = 0; ks < 4; ks++) {
        uint32_t ahi[2][4], alo[2][4];
        #pragma unroll
        for (int mt = 0; mt < 2; mt++) {
            unsigned off = (unsigned)(wm * 32 + mt * 16 + lr) * 144 + (unsigned)(ks * 16 + lh * 8) * 2;
            ldsm4(ahi[mt], whiB + off);
            ldsm4(alo[mt], wloB + off);
        }
        uint32_t bhi[2][4], blo[2][4];
        #pragma unroll
        for (int ng = 0; ng < 2; ng++) {
            unsigned off = (unsigned)(ks * 16 + lr) * 272 + (unsigned)(wn * 32 + ng * 16 + lh * 8) * 2;
            ldsm4t(bhi[ng], xhiB + off);
            ldsm4t(blo[ng], xloB + off);
        }
        #pragma unroll
        for (int mt = 0; mt < 2; mt++)
            #pragma unroll
            for (int ng = 0; ng < 2; ng++) {
                mma16816(acc[mt][2*ng],   ahi[mt], bhi[ng][0], bhi[ng][1]);
                mma16816(acc[mt][2*ng+1], ahi[mt], bhi[ng][2], bhi[ng][3]);
                mma16816(acc[mt][2*ng],   ahi[mt], blo[ng][0], blo[ng][1]);
                mma16816(acc[mt][2*ng+1], ahi[mt], blo[ng][2], blo[ng][3]);
                mma16816(acc[mt][2*ng],   alo[mt], bhi[ng][0], bhi[ng][1]);
                mma16816(acc[mt][2*ng+1], alo[mt], bhi[ng][2], bhi[ng][3]);
            }
    }

    const int qr = lane >> 2, qc = lane & 3;
    float* ob = out + (size_t)bb * 64 * ldRow + j0;
    const float* sb = S + (size_t)bb * 64 * ldRow + j0;
    #pragma unroll
    for (int mt = 0; mt < 2; mt++)
        #pragma unroll
        for (int half = 0; half < 2; half++) {
            const int i = wm * 32 + mt * 16 + qr + half * 8;
            #pragma unroll
            for (int ng = 0; ng < 4; ng++) {
                const int j = wn * 32 + ng * 8 + qc * 2;
                float v0 = acc[mt][ng][half * 2 + 0];
                float v1 = acc[mt][ng][half * 2 + 1];
                if (MOD) {
                    float2 s2 = *(const float2*)(sb + (size_t)i * ldRow + j);
                    v0 *= s2.x; v1 *= s2.y;
                }
                *(float2*)(ob + (size_t)i * ldRow + j) = make_float2(v0, v1);
            }
        }
}

// ================================================================ fused IDCT(w) + LayerNorm + silu-gate + bf16 split
#define DL_SMEM ((4096 + 2*64*392) * 4)
__global__ void __launch_bounds__(256) dct_ln_k(
    const float* __restrict__ X, const float* __restrict__ z,
    const float* __restrict__ gam, const float* __restrict__ bet,
    __nv_bfloat16* __restrict__ dst)
{
    extern __shared__ float s[];
    float* Ws = s;
    float* Xs = s + 4096;
    float* Os = s + 4096 + 64*392;
    const int t = threadIdx.x;
    const int bb = blockIdx.x;

    for (int idx = t; idx < 4096; idx += 256) Ws[idx] = g_W[idx];
    const float* Xb = X + (size_t)bb * 24576;
    for (int f = t; f < 6144; f += 256) {
        int row = f / 96, col = (f - row * 96) * 4;
        *(float4*)&Xs[row * 392 + col] = *(const float4*)(Xb + (size_t)row * 384 + col);
    }
    __syncthreads();

    const int wpair = t >> 3;
    const int cg = t & 7;
    const int w0 = wpair * 2;
    #pragma unroll
    for (int jb = 0; jb < 4; jb++) {
        float a0[12], a1[12];
        #pragma unroll
        for (int j = 0; j < 12; j++) { a0[j] = 0.f; a1[j] = 0.f; }
        #pragma unroll 4
        for (int m = 0; m < 64; m++) {
            float wv0 = Ws[m * 64 + w0];
            float wv1 = Ws[m * 64 + w0 + 1];
            const float* xr = &Xs[m * 392 + cg + 8 * (jb * 12)];
            #pragma unroll
            for (int j = 0; j < 12; j++) {
                float xv = xr[8 * j];
                a0[j] = fmaf(wv0, xv, a0[j]);
                a1[j] = fmaf(wv1, xv, a1[j]);
            }
        }
        #pragma unroll
        for (int j = 0; j < 12; j++) {
            int c = cg + 8 * (jb * 12 + j);
            Os[w0 * 392 + c]       = a0[j];
            Os[(w0 + 1) * 392 + c] = a1[j];
        }
    }
    __syncthreads();

    const int warp = t >> 5, lane = t & 31;
    float gv[12], bv[12];
    #pragma unroll
    for (int k = 0; k < 12; k++) { gv[k] = gam[lane + 32*k]; bv[k] = bet[lane + 32*k]; }
    for (int w = warp; w < 64; w += 8) {
        float vals[12], sum = 0.f;
        #pragma unroll
        for (int k = 0; k < 12; k++) { vals[k] = Os[w * 392 + lane + 32*k]; sum += vals[k]; }
        #pragma unroll
        for (int o = 16; o; o >>= 1) sum += __shfl_xor_sync(0xffffffffu, sum, o);
        float mu = sum * (1.0f / 384.0f);
        float q = 0.f;
        #pragma unroll
        for (int k = 0; k < 12; k++) { float d = vals[k] - mu; q = fmaf(d, d, q); }
        #pragma unroll
        for (int o = 16; o; o >>= 1) q += __shfl_xor_sync(0xffffffffu, q, o);
        float inv = rsqrtf(q * (1.0f / 384.0f) + 1e-5f);
        const size_t pixel = (size_t)bb * 64 + w;
        const float* zr = z + pixel * 384;
        __nv_bfloat16* dr = dst + pixel * 768;
        #pragma unroll
        for (int k = 0; k < 12; k++) {
            int c = lane + 32*k;
            float o = ((vals[k] - mu) * inv * gv[k] + bv[k]) * zr[c];
            __nv_bfloat16 hi, lo; split2(o, hi, lo);
            dr[c] = hi; dr[384 + c] = lo;
        }
    }
}

// ================================================================ launcher
#define TG_SMEM 65536

extern "C" void kernel_launch(void* const* d_in, const int* in_sizes, int n_in,
                              void* d_out, int out_size)
{
    const float* x     = (const float*)d_in[0];
    const float* freq  = (const float*)d_in[1];
    const float* dw_w  = (const float*)d_in[2];
    const float* dw_b  = (const float*)d_in[3];
    const float* lin_w = (const float*)d_in[4];
    const float* lin_b = (const float*)d_in[5];
    const float* tok_w = (const float*)d_in[6];
    const float* tok_b = (const float*)d_in[7];
    const float* ln_g  = (const float*)d_in[8];
    const float* ln_b  = (const float*)d_in[9];
    const float* out_w = (const float*)d_in[10];
    const float* out_b = (const float*)d_in[11];
    const float* cp    = (const float*)d_in[12];
    const float* ap    = (const float*)d_in[13];
    float* out = (float*)d_out;

    float *pxs, *pz, *ps, *pf1;
    __nv_bfloat16 *pxd, *pfq, *pf2, *pwl, *pwt, *pwo;
    cudaGetSymbolAddress((void**)&pxs, g_xs);
    cudaGetSymbolAddress((void**)&pz,  g_z);
    cudaGetSymbolAddress((void**)&ps,  g_s);
    cudaGetSymbolAddress((void**)&pf1, g_f1);
    cudaGetSymbolAddress((void**)&pxd, g_xd);
    cudaGetSymbolAddress((void**)&pfq, g_fq);
    cudaGetSymbolAddress((void**)&pf2, g_f2);
    cudaGetSymbolAddress((void**)&pwl, g_wl);
    cudaGetSymbolAddress((void**)&pwt, g_wt);
    cudaGetSymbolAddress((void**)&pwo, g_wo);

    cudaFuncSetAttribute((const void*)tgemm_k<0>, cudaFuncAttributeMaxDynamicSharedMemorySize, TG_SMEM);
    cudaFuncSetAttribute((const void*)tgemm_k<1>, cudaFuncAttributeMaxDynamicSharedMemorySize, TG_SMEM);
    cudaFuncSetAttribute((const void*)tgemm_k<2>, cudaFuncAttributeMaxDynamicSharedMemorySize, TG_SMEM);
    cudaFuncSetAttribute((const void*)(dctT_k<true,  false>), cudaFuncAttributeMaxDynamicSharedMemorySize, DT_SMEM);
    cudaFuncSetAttribute((const void*)(dctT_k<true,  true >), cudaFuncAttributeMaxDynamicSharedMemorySize, DT_SMEM);
    cudaFuncSetAttribute((const void*)(dctT_k<false, false>), cudaFuncAttributeMaxDynamicSharedMemorySize, DT_SMEM);
    cudaFuncSetAttribute((const void*)dct_ln_k,   cudaFuncAttributeMaxDynamicSharedMemorySize, DL_SMEM);

    build_w_k<<<16, 256>>>();
    split_k<<<(768*96 + 255)/256, 256>>>(lin_w, pwl, 768*96);
    split_k<<<(384*96 + 255)/256, 256>>>(tok_w, pwt, 384*96);
    split_k<<<(384*96 + 255)/256, 256>>>(out_w, pwo, 384*96);
    split_k<<<(65536*96 + 255)/256, 256>>>(freq, pfq, 65536*96);
    dwconv_k<<<1024, 384>>>(x, dw_w, dw_b, pxd);
    // xz = xd @ lin_w^T : xs + silu(z)
    tgemm_k<0><<<dim3(6, 512), 256, TG_SMEM>>>(pxd, pwl, lin_b, pxs, pz, nullptr, nullptr);
    // s = modulation(gelu(freq @ tok_w^T))
    tgemm_k<1><<<dim3(3, 512), 256, TG_SMEM>>>(pfq, pwt, tok_b, ps, nullptr, cp, ap);
    // DCT over h (tensorized)
    dctT_k<true,  false><<<dim3(192, 16),   256, DT_SMEM>>>(pf1, pxs, pf1, 24576);
    // DCT over w + modulate by s (tensorized)
    dctT_k<true,  true ><<<dim3(3,  1024),  256, DT_SMEM>>>((float*)pf2, pf1, ps, 384);
    // IDCT over n (tensorized)
    dctT_k<false, false><<<dim3(192, 16),   256, DT_SMEM>>>(pf1, (float*)pf2, pf1, 24576);
    // fused IDCT over m + LayerNorm + silu-gate -> split bf16
    dct_ln_k<<<1024, 256, DL_SMEM>>>(pf1, pz, ln_g, ln_b, pf2);
    // out = xo @ out_w^T + out_b
    tgemm_k<2><<<dim3(3, 512), 256, TG_SMEM>>>(pf2, pwo, out_b, out, nullptr, nullptr, nullptr);
}